// round 13
// baseline (speedup 1.0000x reference)
#include <cuda_runtime.h>
#include <cuda_fp16.h>
#include <cstdint>

#define NN 100000
#define NE 1600000
#define F  128
#define SCAN_BLK 1024
#define NBLK ((NN + SCAN_BLK - 1) / SCAN_BLK)   // 98

// Scratch (allocation-free rule: __device__ globals)
__device__ float   g_h[(size_t)NN * F];     // h = x @ W (fp32, self-loop path)
__device__ __half2 g_h16[(size_t)NN * (F/2)]; // fp16 copy (neighbor messages)
__device__ float   g_dinv[NN];
__device__ int     g_deg[NN];
__device__ int     g_src[NE];
__device__ int     g_dst[NE];
__device__ int     g_rowstart[NN + 1];
__device__ int     g_cursor[NN];
__device__ int     g_csr_src[NE];
__device__ int     g_bsum[128];
__device__ int     g_is64;

// --------------------------- detect edge dtype + zero degree (fused) --------
__global__ void k_detect_zero(const int* __restrict__ ei32) {
    int i = blockIdx.x * blockDim.x + threadIdx.x;
    if (i < NN) g_deg[i] = 0;
    if (blockIdx.x == 0) {
        __shared__ int nz;
        if (threadIdx.x == 0) nz = 0;
        __syncthreads();
        for (int k = threadIdx.x; k < 8192; k += blockDim.x)
            if (ei32[2 * k + 1] != 0) nz = 1;
        __syncthreads();
        if (threadIdx.x == 0) g_is64 = (nz == 0) ? 1 : 0;
    }
}

// Materialize src/dst as int32; count in-degree for dst on the fly.
__global__ void k_convert(const void* __restrict__ ei) {
    long long t = (long long)blockIdx.x * blockDim.x + threadIdx.x;
    if (t >= 2LL * NE) return;
    int v;
    if (g_is64) v = (int)((const long long*)ei)[t];
    else        v = ((const int*)ei)[t];
    if (t < NE) g_src[t] = v;
    else { g_dst[t - NE] = v; atomicAdd(&g_deg[v], 1); }
}

// -------------------------------------- exclusive scan (+ dinv fused) -------
__global__ __launch_bounds__(256) void k_scan1() {
    __shared__ int sh[256];
    int t = threadIdx.x;
    int base = blockIdx.x * SCAN_BLK + t * 4;
    int v0 = 0, v1 = 0, v2 = 0, v3 = 0;
    if (base + 3 < NN) {
        int4 d = *(const int4*)&g_deg[base];
        v0 = d.x; v1 = d.y; v2 = d.z; v3 = d.w;
    } else {
        if (base + 0 < NN) v0 = g_deg[base + 0];
        if (base + 1 < NN) v1 = g_deg[base + 1];
        if (base + 2 < NN) v2 = g_deg[base + 2];
        if (base + 3 < NN) v3 = g_deg[base + 3];
    }
    // fused dinv (self-loop adds 1 to degree)
    if (base + 0 < NN) g_dinv[base + 0] = rsqrtf((float)(v0 + 1));
    if (base + 1 < NN) g_dinv[base + 1] = rsqrtf((float)(v1 + 1));
    if (base + 2 < NN) g_dinv[base + 2] = rsqrtf((float)(v2 + 1));
    if (base + 3 < NN) g_dinv[base + 3] = rsqrtf((float)(v3 + 1));

    int s = v0 + v1 + v2 + v3;
    sh[t] = s;
    __syncthreads();
#pragma unroll
    for (int off = 1; off < 256; off <<= 1) {
        int x = (t >= off) ? sh[t - off] : 0;
        __syncthreads();
        sh[t] += x;
        __syncthreads();
    }
    int excl = sh[t] - s;
    if (t == 255) g_bsum[blockIdx.x] = sh[255];
    if (base + 0 < NN) g_rowstart[base + 0] = excl;
    if (base + 1 < NN) g_rowstart[base + 1] = excl + v0;
    if (base + 2 < NN) g_rowstart[base + 2] = excl + v0 + v1;
    if (base + 3 < NN) g_rowstart[base + 3] = excl + v0 + v1 + v2;
}

__global__ void k_scan2() {
    __shared__ int sh[128];
    int t = threadIdx.x;  // 128 threads
    int v = (t < NBLK) ? g_bsum[t] : 0;
    sh[t] = v;
    __syncthreads();
#pragma unroll
    for (int off = 1; off < 128; off <<= 1) {
        int x = (t >= off) ? sh[t - off] : 0;
        __syncthreads();
        sh[t] += x;
        __syncthreads();
    }
    if (t < NBLK) g_bsum[t] = sh[t] - v;  // exclusive
    if (t == 0) g_rowstart[NN] = NE;
}

__global__ void k_scan3() {
    int i = blockIdx.x * blockDim.x + threadIdx.x;
    if (i < NN) {
        g_rowstart[i] += g_bsum[i / SCAN_BLK];
        g_cursor[i] = 0;
    }
}

// --------------------------------------------------------------- CSR fill ---
__global__ void k_fill() {
    int e = blockIdx.x * blockDim.x + threadIdx.x;
    if (e >= NE) return;
    int d = g_dst[e];
    int pos = g_rowstart[d] + atomicAdd(&g_cursor[d], 1);
    g_csr_src[pos] = g_src[e];
}

// ------------------------------------------------------ GEMM (3x tf32 MMA) --
__device__ __forceinline__ uint32_t f2tf32(float x) {
    uint32_t r;
    asm("cvt.rna.tf32.f32 %0, %1;" : "=r"(r) : "f"(x));
    return r;
}

__device__ __forceinline__ void mma8(float* c, const uint32_t* a,
                                     uint32_t b0, uint32_t b1) {
    asm volatile(
        "mma.sync.aligned.m16n8k8.row.col.f32.tf32.tf32.f32 "
        "{%0,%1,%2,%3}, {%4,%5,%6,%7}, {%8,%9}, {%0,%1,%2,%3};"
        : "+f"(c[0]), "+f"(c[1]), "+f"(c[2]), "+f"(c[3])
        : "r"(a[0]), "r"(a[1]), "r"(a[2]), "r"(a[3]), "r"(b0), "r"(b1));
}

#define BK 16
#define APAD 20
#define BPAD 136

__global__ __launch_bounds__(256) void k_gemm(const float* __restrict__ X,
                                              const float* __restrict__ W) {
    __shared__ uint32_t Ah[128 * APAD], Al[128 * APAD];
    __shared__ uint32_t Bh[BK * BPAD],  Bl[BK * BPAD];

    int tid  = threadIdx.x;
    int lane = tid & 31;
    int w    = tid >> 5;
    int wm   = w >> 1;
    int wn   = w & 1;
    int gr   = lane >> 2;
    int gc   = lane & 3;
    int row0 = blockIdx.x * 128;

    float acc[2][8][4];
#pragma unroll
    for (int i = 0; i < 2; i++)
#pragma unroll
        for (int j = 0; j < 8; j++)
#pragma unroll
            for (int q = 0; q < 4; q++) acc[i][j][q] = 0.0f;

    for (int k0 = 0; k0 < 128; k0 += BK) {
#pragma unroll
        for (int r = 0; r < 2; r++) {
            int idx = tid + r * 256;
            int m   = idx >> 2;
            int kq  = (idx & 3) * 4;
            float4 v = (row0 + m < NN)
                ? *(const float4*)(X + (size_t)(row0 + m) * F + k0 + kq)
                : make_float4(0.f, 0.f, 0.f, 0.f);
            float vv[4] = {v.x, v.y, v.z, v.w};
#pragma unroll
            for (int q = 0; q < 4; q++) {
                uint32_t hi = f2tf32(vv[q]);
                float lo = vv[q] - __uint_as_float(hi);
                Ah[m * APAD + kq + q] = hi;
                Al[m * APAD + kq + q] = f2tf32(lo);
            }
        }
#pragma unroll
        for (int r = 0; r < 2; r++) {
            int idx = tid + r * 256;
            int k   = idx >> 5;
            int nq  = (idx & 31) * 4;
            float4 v = *(const float4*)(W + (size_t)(k0 + k) * F + nq);
            float vv[4] = {v.x, v.y, v.z, v.w};
#pragma unroll
            for (int q = 0; q < 4; q++) {
                uint32_t hi = f2tf32(vv[q]);
                float lo = vv[q] - __uint_as_float(hi);
                Bh[k * BPAD + nq + q] = hi;
                Bl[k * BPAD + nq + q] = f2tf32(lo);
            }
        }
        __syncthreads();

#pragma unroll
        for (int ks = 0; ks < BK; ks += 8) {
            uint32_t a_hi[2][4], a_lo[2][4];
#pragma unroll
            for (int i = 0; i < 2; i++) {
                int mb = wm * 32 + i * 16;
                a_hi[i][0] = Ah[(mb + gr)     * APAD + ks + gc];
                a_hi[i][1] = Ah[(mb + gr + 8) * APAD + ks + gc];
                a_hi[i][2] = Ah[(mb + gr)     * APAD + ks + gc + 4];
                a_hi[i][3] = Ah[(mb + gr + 8) * APAD + ks + gc + 4];
                a_lo[i][0] = Al[(mb + gr)     * APAD + ks + gc];
                a_lo[i][1] = Al[(mb + gr + 8) * APAD + ks + gc];
                a_lo[i][2] = Al[(mb + gr)     * APAD + ks + gc + 4];
                a_lo[i][3] = Al[(mb + gr + 8) * APAD + ks + gc + 4];
            }
#pragma unroll
            for (int j = 0; j < 8; j++) {
                int nb = wn * 64 + j * 8;
                uint32_t bh0 = Bh[(ks + gc)     * BPAD + nb + gr];
                uint32_t bh1 = Bh[(ks + gc + 4) * BPAD + nb + gr];
                uint32_t bl0 = Bl[(ks + gc)     * BPAD + nb + gr];
                uint32_t bl1 = Bl[(ks + gc + 4) * BPAD + nb + gr];
#pragma unroll
                for (int i = 0; i < 2; i++) {
                    mma8(acc[i][j], a_hi[i], bh0, bh1);
                    mma8(acc[i][j], a_hi[i], bl0, bl1);
                    mma8(acc[i][j], a_lo[i], bh0, bh1);
                }
            }
        }
        __syncthreads();
    }

    // Epilogue: fp32 h + fp16 copy for neighbor gather
#pragma unroll
    for (int i = 0; i < 2; i++) {
        int rbase = row0 + wm * 32 + i * 16;
#pragma unroll
        for (int j = 0; j < 8; j++) {
            int col = wn * 64 + j * 8 + 2 * gc;
            int r1 = rbase + gr;
            int r2 = rbase + gr + 8;
            if (r1 < NN) {
                *(float2*)(g_h + (size_t)r1 * F + col) =
                    make_float2(acc[i][j][0], acc[i][j][1]);
                g_h16[(size_t)r1 * (F/2) + col/2] =
                    __floats2half2_rn(acc[i][j][0], acc[i][j][1]);
            }
            if (r2 < NN) {
                *(float2*)(g_h + (size_t)r2 * F + col) =
                    make_float2(acc[i][j][2], acc[i][j][3]);
                g_h16[(size_t)r2 * (F/2) + col/2] =
                    __floats2half2_rn(acc[i][j][2], acc[i][j][3]);
            }
        }
    }
}

// ---------------------------------------------------------------- gather ----
// One warp per destination node. Self-loop term fp32, neighbor messages fp16
// (halves L2 traffic). Each lane owns 4 consecutive features.
__global__ __launch_bounds__(256) void k_gather(float* __restrict__ out,
                                                const float* __restrict__ b) {
    int node = (blockIdx.x * 256 + threadIdx.x) >> 5;
    if (node >= NN) return;
    int lane = threadIdx.x & 31;

    float di = g_dinv[node];
    float4 hv = ((const float4*)(g_h + (size_t)node * F))[lane];
    float sl = di * di;
    float ax = hv.x * sl, ay = hv.y * sl, az = hv.z * sl, aw = hv.w * sl;

    int beg = g_rowstart[node];
    int end = g_rowstart[node + 1];
    int e = beg;
    for (; e + 4 <= end; e += 4) {
        int s0 = g_csr_src[e + 0];
        int s1 = g_csr_src[e + 1];
        int s2 = g_csr_src[e + 2];
        int s3 = g_csr_src[e + 3];
        float n0 = di * g_dinv[s0];
        float n1 = di * g_dinv[s1];
        float n2 = di * g_dinv[s2];
        float n3 = di * g_dinv[s3];
        __half2 p0a = g_h16[(size_t)s0 * (F/2) + 2*lane];
        __half2 p0b = g_h16[(size_t)s0 * (F/2) + 2*lane + 1];
        __half2 p1a = g_h16[(size_t)s1 * (F/2) + 2*lane];
        __half2 p1b = g_h16[(size_t)s1 * (F/2) + 2*lane + 1];
        __half2 p2a = g_h16[(size_t)s2 * (F/2) + 2*lane];
        __half2 p2b = g_h16[(size_t)s2 * (F/2) + 2*lane + 1];
        __half2 p3a = g_h16[(size_t)s3 * (F/2) + 2*lane];
        __half2 p3b = g_h16[(size_t)s3 * (F/2) + 2*lane + 1];
        float2 f0a = __half22float2(p0a), f0b = __half22float2(p0b);
        float2 f1a = __half22float2(p1a), f1b = __half22float2(p1b);
        float2 f2a = __half22float2(p2a), f2b = __half22float2(p2b);
        float2 f3a = __half22float2(p3a), f3b = __half22float2(p3b);
        ax = fmaf(f0a.x, n0, fmaf(f1a.x, n1, fmaf(f2a.x, n2, fmaf(f3a.x, n3, ax))));
        ay = fmaf(f0a.y, n0, fmaf(f1a.y, n1, fmaf(f2a.y, n2, fmaf(f3a.y, n3, ay))));
        az = fmaf(f0b.x, n0, fmaf(f1b.x, n1, fmaf(f2b.x, n2, fmaf(f3b.x, n3, az))));
        aw = fmaf(f0b.y, n0, fmaf(f1b.y, n1, fmaf(f2b.y, n2, fmaf(f3b.y, n3, aw))));
    }
    for (; e < end; e++) {
        int s = g_csr_src[e];
        float n = di * g_dinv[s];
        __half2 pa = g_h16[(size_t)s * (F/2) + 2*lane];
        __half2 pb = g_h16[(size_t)s * (F/2) + 2*lane + 1];
        float2 fa = __half22float2(pa), fb = __half22float2(pb);
        ax = fmaf(fa.x, n, ax);
        ay = fmaf(fa.y, n, ay);
        az = fmaf(fb.x, n, az);
        aw = fmaf(fb.y, n, aw);
    }

    float4 bv = ((const float4*)b)[lane];
    ((float4*)(out + (size_t)node * F))[lane] =
        make_float4(ax + bv.x, ay + bv.y, az + bv.z, aw + bv.w);
}

// ------------------------------------------------------------------ launch --
extern "C" void kernel_launch(void* const* d_in, const int* in_sizes, int n_in,
                              void* d_out, int out_size) {
    const float* x  = (const float*)d_in[0];   // [NN, F]
    const void*  ei = d_in[1];                 // [2, NE], int32 or int64
    const float* W  = (const float*)d_in[2];   // [F, F]
    const float* b  = (const float*)d_in[3];   // [F]
    float* out = (float*)d_out;                // [NN, F]

    k_detect_zero<<<(NN + 255) / 256, 256>>>((const int*)ei);
    k_convert<<<(int)((2LL * NE + 255) / 256), 256>>>(ei);

    k_scan1<<<NBLK, 256>>>();
    k_scan2<<<1, 128>>>();
    k_scan3<<<(NN + 255) / 256, 256>>>();
    k_fill<<<(NE + 255) / 256, 256>>>();

    k_gemm<<<(NN + 127) / 128, 256>>>(x, W);

    k_gather<<<(NN * 32 + 255) / 256, 256>>>(out, b);
}

// round 14
// speedup vs baseline: 1.4235x; 1.4235x over previous
#include <cuda_runtime.h>
#include <cuda_fp16.h>
#include <cstdint>

#define NN 100000
#define NE 1600000
#define F  128
#define SCAN_BLK 1024
#define NBLK ((NN + SCAN_BLK - 1) / SCAN_BLK)   // 98

// Scratch (allocation-free rule: __device__ globals)
__device__ float   g_h[(size_t)NN * F];     // h = x @ W (fp32, self-loop path)
__device__ __half2 g_h16[(size_t)NN * (F/2)]; // fp16 copy (neighbor messages)
__device__ float   g_dinv[NN];
__device__ int     g_deg[NN];
__device__ int     g_src[NE];
__device__ int     g_dst[NE];
__device__ int     g_rowstart[NN + 1];
__device__ int     g_cursor[NN];
__device__ int     g_csr_src[NE];
__device__ int     g_bsum[128];
__device__ int     g_is64;

// --------------------------- detect edge dtype + zero degree (fused) --------
__global__ void k_detect_zero(const int* __restrict__ ei32) {
    int i = blockIdx.x * blockDim.x + threadIdx.x;
    if (i < NN) g_deg[i] = 0;
    if (blockIdx.x == 0) {
        __shared__ int nz;
        if (threadIdx.x == 0) nz = 0;
        __syncthreads();
        for (int k = threadIdx.x; k < 8192; k += blockDim.x)
            if (ei32[2 * k + 1] != 0) nz = 1;
        __syncthreads();
        if (threadIdx.x == 0) g_is64 = (nz == 0) ? 1 : 0;
    }
}

// Materialize src/dst as int32; count in-degree for dst on the fly.
__global__ void k_convert(const void* __restrict__ ei) {
    long long t = (long long)blockIdx.x * blockDim.x + threadIdx.x;
    if (t >= 2LL * NE) return;
    int v;
    if (g_is64) v = (int)((const long long*)ei)[t];
    else        v = ((const int*)ei)[t];
    if (t < NE) g_src[t] = v;
    else { g_dst[t - NE] = v; atomicAdd(&g_deg[v], 1); }
}

// -------------------------------------- exclusive scan (+ dinv fused) -------
__global__ __launch_bounds__(256) void k_scan1() {
    __shared__ int sh[256];
    int t = threadIdx.x;
    int base = blockIdx.x * SCAN_BLK + t * 4;
    int v0 = 0, v1 = 0, v2 = 0, v3 = 0;
    if (base + 3 < NN) {
        int4 d = *(const int4*)&g_deg[base];
        v0 = d.x; v1 = d.y; v2 = d.z; v3 = d.w;
    } else {
        if (base + 0 < NN) v0 = g_deg[base + 0];
        if (base + 1 < NN) v1 = g_deg[base + 1];
        if (base + 2 < NN) v2 = g_deg[base + 2];
        if (base + 3 < NN) v3 = g_deg[base + 3];
    }
    // fused dinv (self-loop adds 1 to degree)
    if (base + 0 < NN) g_dinv[base + 0] = rsqrtf((float)(v0 + 1));
    if (base + 1 < NN) g_dinv[base + 1] = rsqrtf((float)(v1 + 1));
    if (base + 2 < NN) g_dinv[base + 2] = rsqrtf((float)(v2 + 1));
    if (base + 3 < NN) g_dinv[base + 3] = rsqrtf((float)(v3 + 1));

    int s = v0 + v1 + v2 + v3;
    sh[t] = s;
    __syncthreads();
#pragma unroll
    for (int off = 1; off < 256; off <<= 1) {
        int x = (t >= off) ? sh[t - off] : 0;
        __syncthreads();
        sh[t] += x;
        __syncthreads();
    }
    int excl = sh[t] - s;
    if (t == 255) g_bsum[blockIdx.x] = sh[255];
    if (base + 0 < NN) g_rowstart[base + 0] = excl;
    if (base + 1 < NN) g_rowstart[base + 1] = excl + v0;
    if (base + 2 < NN) g_rowstart[base + 2] = excl + v0 + v1;
    if (base + 3 < NN) g_rowstart[base + 3] = excl + v0 + v1 + v2;
}

__global__ void k_scan2() {
    __shared__ int sh[128];
    int t = threadIdx.x;  // 128 threads
    int v = (t < NBLK) ? g_bsum[t] : 0;
    sh[t] = v;
    __syncthreads();
#pragma unroll
    for (int off = 1; off < 128; off <<= 1) {
        int x = (t >= off) ? sh[t - off] : 0;
        __syncthreads();
        sh[t] += x;
        __syncthreads();
    }
    if (t < NBLK) g_bsum[t] = sh[t] - v;  // exclusive
    if (t == 0) g_rowstart[NN] = NE;
}

__global__ void k_scan3() {
    int i = blockIdx.x * blockDim.x + threadIdx.x;
    if (i < NN) {
        g_rowstart[i] += g_bsum[i / SCAN_BLK];
        g_cursor[i] = 0;
    }
}

// --------------------------------------------------------------- CSR fill ---
__global__ void k_fill() {
    int e = blockIdx.x * blockDim.x + threadIdx.x;
    if (e >= NE) return;
    int d = g_dst[e];
    int pos = g_rowstart[d] + atomicAdd(&g_cursor[d], 1);
    g_csr_src[pos] = g_src[e];
}

// ------------------------------------------------------ GEMM (3x tf32 MMA) --
__device__ __forceinline__ uint32_t f2tf32(float x) {
    uint32_t r;
    asm("cvt.rna.tf32.f32 %0, %1;" : "=r"(r) : "f"(x));
    return r;
}

__device__ __forceinline__ void mma8(float* c, const uint32_t* a,
                                     uint32_t b0, uint32_t b1) {
    asm volatile(
        "mma.sync.aligned.m16n8k8.row.col.f32.tf32.tf32.f32 "
        "{%0,%1,%2,%3}, {%4,%5,%6,%7}, {%8,%9}, {%0,%1,%2,%3};"
        : "+f"(c[0]), "+f"(c[1]), "+f"(c[2]), "+f"(c[3])
        : "r"(a[0]), "r"(a[1]), "r"(a[2]), "r"(a[3]), "r"(b0), "r"(b1));
}

#define BK 16
#define APAD 20
#define BPAD 136

__global__ __launch_bounds__(256) void k_gemm(const float* __restrict__ X,
                                              const float* __restrict__ W) {
    __shared__ uint32_t Ah[128 * APAD], Al[128 * APAD];
    __shared__ uint32_t Bh[BK * BPAD],  Bl[BK * BPAD];

    int tid  = threadIdx.x;
    int lane = tid & 31;
    int w    = tid >> 5;
    int wm   = w >> 1;
    int wn   = w & 1;
    int gr   = lane >> 2;
    int gc   = lane & 3;
    int row0 = blockIdx.x * 128;

    float acc[2][8][4];
#pragma unroll
    for (int i = 0; i < 2; i++)
#pragma unroll
        for (int j = 0; j < 8; j++)
#pragma unroll
            for (int q = 0; q < 4; q++) acc[i][j][q] = 0.0f;

    for (int k0 = 0; k0 < 128; k0 += BK) {
#pragma unroll
        for (int r = 0; r < 2; r++) {
            int idx = tid + r * 256;
            int m   = idx >> 2;
            int kq  = (idx & 3) * 4;
            float4 v = (row0 + m < NN)
                ? *(const float4*)(X + (size_t)(row0 + m) * F + k0 + kq)
                : make_float4(0.f, 0.f, 0.f, 0.f);
            float vv[4] = {v.x, v.y, v.z, v.w};
#pragma unroll
            for (int q = 0; q < 4; q++) {
                uint32_t hi = f2tf32(vv[q]);
                float lo = vv[q] - __uint_as_float(hi);
                Ah[m * APAD + kq + q] = hi;
                Al[m * APAD + kq + q] = f2tf32(lo);
            }
        }
#pragma unroll
        for (int r = 0; r < 2; r++) {
            int idx = tid + r * 256;
            int k   = idx >> 5;
            int nq  = (idx & 31) * 4;
            float4 v = *(const float4*)(W + (size_t)(k0 + k) * F + nq);
            float vv[4] = {v.x, v.y, v.z, v.w};
#pragma unroll
            for (int q = 0; q < 4; q++) {
                uint32_t hi = f2tf32(vv[q]);
                float lo = vv[q] - __uint_as_float(hi);
                Bh[k * BPAD + nq + q] = hi;
                Bl[k * BPAD + nq + q] = f2tf32(lo);
            }
        }
        __syncthreads();

#pragma unroll
        for (int ks = 0; ks < BK; ks += 8) {
            uint32_t a_hi[2][4], a_lo[2][4];
#pragma unroll
            for (int i = 0; i < 2; i++) {
                int mb = wm * 32 + i * 16;
                a_hi[i][0] = Ah[(mb + gr)     * APAD + ks + gc];
                a_hi[i][1] = Ah[(mb + gr + 8) * APAD + ks + gc];
                a_hi[i][2] = Ah[(mb + gr)     * APAD + ks + gc + 4];
                a_hi[i][3] = Ah[(mb + gr + 8) * APAD + ks + gc + 4];
                a_lo[i][0] = Al[(mb + gr)     * APAD + ks + gc];
                a_lo[i][1] = Al[(mb + gr + 8) * APAD + ks + gc];
                a_lo[i][2] = Al[(mb + gr)     * APAD + ks + gc + 4];
                a_lo[i][3] = Al[(mb + gr + 8) * APAD + ks + gc + 4];
            }
#pragma unroll
            for (int j = 0; j < 8; j++) {
                int nb = wn * 64 + j * 8;
                uint32_t bh0 = Bh[(ks + gc)     * BPAD + nb + gr];
                uint32_t bh1 = Bh[(ks + gc + 4) * BPAD + nb + gr];
                uint32_t bl0 = Bl[(ks + gc)     * BPAD + nb + gr];
                uint32_t bl1 = Bl[(ks + gc + 4) * BPAD + nb + gr];
#pragma unroll
                for (int i = 0; i < 2; i++) {
                    mma8(acc[i][j], a_hi[i], bh0, bh1);
                    mma8(acc[i][j], a_hi[i], bl0, bl1);
                    mma8(acc[i][j], a_lo[i], bh0, bh1);
                }
            }
        }
        __syncthreads();
    }

    // Epilogue: fp32 h + fp16 copy for neighbor gather
#pragma unroll
    for (int i = 0; i < 2; i++) {
        int rbase = row0 + wm * 32 + i * 16;
#pragma unroll
        for (int j = 0; j < 8; j++) {
            int col = wn * 64 + j * 8 + 2 * gc;
            int r1 = rbase + gr;
            int r2 = rbase + gr + 8;
            if (r1 < NN) {
                *(float2*)(g_h + (size_t)r1 * F + col) =
                    make_float2(acc[i][j][0], acc[i][j][1]);
                g_h16[(size_t)r1 * (F/2) + col/2] =
                    __floats2half2_rn(acc[i][j][0], acc[i][j][1]);
            }
            if (r2 < NN) {
                *(float2*)(g_h + (size_t)r2 * F + col) =
                    make_float2(acc[i][j][2], acc[i][j][3]);
                g_h16[(size_t)r2 * (F/2) + col/2] =
                    __floats2half2_rn(acc[i][j][2], acc[i][j][3]);
            }
        }
    }
}

// ---------------------------------------------------------------- gather ----
// One warp per destination node. Self-loop term fp32, neighbor messages fp16
// (halves L2 traffic). Each lane owns 4 consecutive features.
__global__ __launch_bounds__(256) void k_gather(float* __restrict__ out,
                                                const float* __restrict__ b) {
    int node = (blockIdx.x * 256 + threadIdx.x) >> 5;
    if (node >= NN) return;
    int lane = threadIdx.x & 31;

    float di = g_dinv[node];
    float4 hv = ((const float4*)(g_h + (size_t)node * F))[lane];
    float sl = di * di;
    float ax = hv.x * sl, ay = hv.y * sl, az = hv.z * sl, aw = hv.w * sl;

    int beg = g_rowstart[node];
    int end = g_rowstart[node + 1];
    int e = beg;
    for (; e + 4 <= end; e += 4) {
        int s0 = g_csr_src[e + 0];
        int s1 = g_csr_src[e + 1];
        int s2 = g_csr_src[e + 2];
        int s3 = g_csr_src[e + 3];
        float n0 = di * g_dinv[s0];
        float n1 = di * g_dinv[s1];
        float n2 = di * g_dinv[s2];
        float n3 = di * g_dinv[s3];
        __half2 p0a = g_h16[(size_t)s0 * (F/2) + 2*lane];
        __half2 p0b = g_h16[(size_t)s0 * (F/2) + 2*lane + 1];
        __half2 p1a = g_h16[(size_t)s1 * (F/2) + 2*lane];
        __half2 p1b = g_h16[(size_t)s1 * (F/2) + 2*lane + 1];
        __half2 p2a = g_h16[(size_t)s2 * (F/2) + 2*lane];
        __half2 p2b = g_h16[(size_t)s2 * (F/2) + 2*lane + 1];
        __half2 p3a = g_h16[(size_t)s3 * (F/2) + 2*lane];
        __half2 p3b = g_h16[(size_t)s3 * (F/2) + 2*lane + 1];
        float2 f0a = __half22float2(p0a), f0b = __half22float2(p0b);
        float2 f1a = __half22float2(p1a), f1b = __half22float2(p1b);
        float2 f2a = __half22float2(p2a), f2b = __half22float2(p2b);
        float2 f3a = __half22float2(p3a), f3b = __half22float2(p3b);
        ax = fmaf(f0a.x, n0, fmaf(f1a.x, n1, fmaf(f2a.x, n2, fmaf(f3a.x, n3, ax))));
        ay = fmaf(f0a.y, n0, fmaf(f1a.y, n1, fmaf(f2a.y, n2, fmaf(f3a.y, n3, ay))));
        az = fmaf(f0b.x, n0, fmaf(f1b.x, n1, fmaf(f2b.x, n2, fmaf(f3b.x, n3, az))));
        aw = fmaf(f0b.y, n0, fmaf(f1b.y, n1, fmaf(f2b.y, n2, fmaf(f3b.y, n3, aw))));
    }
    for (; e < end; e++) {
        int s = g_csr_src[e];
        float n = di * g_dinv[s];
        __half2 pa = g_h16[(size_t)s * (F/2) + 2*lane];
        __half2 pb = g_h16[(size_t)s * (F/2) + 2*lane + 1];
        float2 fa = __half22float2(pa), fb = __half22float2(pb);
        ax = fmaf(fa.x, n, ax);
        ay = fmaf(fa.y, n, ay);
        az = fmaf(fb.x, n, az);
        aw = fmaf(fb.y, n, aw);
    }

    float4 bv = ((const float4*)b)[lane];
    ((float4*)(out + (size_t)node * F))[lane] =
        make_float4(ax + bv.x, ay + bv.y, az + bv.z, aw + bv.w);
}

// ------------------------------------------------------------------ launch --
extern "C" void kernel_launch(void* const* d_in, const int* in_sizes, int n_in,
                              void* d_out, int out_size) {
    const float* x  = (const float*)d_in[0];   // [NN, F]
    const void*  ei = d_in[1];                 // [2, NE], int32 or int64
    const float* W  = (const float*)d_in[2];   // [F, F]
    const float* b  = (const float*)d_in[3];   // [F]
    float* out = (float*)d_out;                // [NN, F]

    k_detect_zero<<<(NN + 255) / 256, 256>>>((const int*)ei);
    k_convert<<<(int)((2LL * NE + 255) / 256), 256>>>(ei);

    k_scan1<<<NBLK, 256>>>();
    k_scan2<<<1, 128>>>();
    k_scan3<<<(NN + 255) / 256, 256>>>();
    k_fill<<<(NE + 255) / 256, 256>>>();

    k_gemm<<<(NN + 127) / 128, 256>>>(x, W);

    k_gather<<<(NN * 32 + 255) / 256, 256>>>(out, b);
}

// round 15
// speedup vs baseline: 1.8502x; 1.2997x over previous
#include <cuda_runtime.h>
#include <cstdint>

#define NN 100000
#define NE 1600000
#define F  128
#define SCAN_BLK 1024
#define NBLK ((NN + SCAN_BLK - 1) / SCAN_BLK)   // 98

// Scratch (allocation-free rule: __device__ globals)
__device__ float g_h[(size_t)NN * F];   // h = x @ W
__device__ float g_dinv[NN];
__device__ int   g_deg[NN];
__device__ int   g_rowstart[NN + 1];
__device__ int   g_cursor[NN];
__device__ int   g_csr_src[NE];
__device__ int   g_bsum[128];
__device__ int   g_is64;

// --------------------------- detect edge dtype + zero degree (fused) --------
__global__ void k_detect_zero(const int* __restrict__ ei32) {
    int i = blockIdx.x * blockDim.x + threadIdx.x;
    if (i < NN) g_deg[i] = 0;
    if (blockIdx.x == 0) {
        __shared__ int nz;
        if (threadIdx.x == 0) nz = 0;
        __syncthreads();
        for (int k = threadIdx.x; k < 8192; k += blockDim.x)
            if (ei32[2 * k + 1] != 0) nz = 1;
        __syncthreads();
        if (threadIdx.x == 0) g_is64 = (nz == 0) ? 1 : 0;
    }
}

// ------------------------------- degree count (reads dst half directly) -----
__global__ void k_count(const void* __restrict__ ei) {
    int e = blockIdx.x * blockDim.x + threadIdx.x;
    if (e >= NE) return;
    int v = g_is64 ? (int)((const long long*)ei)[NE + e]
                   : ((const int*)ei)[NE + e];
    atomicAdd(&g_deg[v], 1);
}

// -------------------------------------- exclusive scan (+ dinv fused) -------
__global__ __launch_bounds__(256) void k_scan1() {
    __shared__ int sh[256];
    int t = threadIdx.x;
    int base = blockIdx.x * SCAN_BLK + t * 4;
    int v0 = 0, v1 = 0, v2 = 0, v3 = 0;
    if (base + 3 < NN) {
        int4 d = *(const int4*)&g_deg[base];
        v0 = d.x; v1 = d.y; v2 = d.z; v3 = d.w;
    } else {
        if (base + 0 < NN) v0 = g_deg[base + 0];
        if (base + 1 < NN) v1 = g_deg[base + 1];
        if (base + 2 < NN) v2 = g_deg[base + 2];
        if (base + 3 < NN) v3 = g_deg[base + 3];
    }
    if (base + 0 < NN) g_dinv[base + 0] = rsqrtf((float)(v0 + 1));
    if (base + 1 < NN) g_dinv[base + 1] = rsqrtf((float)(v1 + 1));
    if (base + 2 < NN) g_dinv[base + 2] = rsqrtf((float)(v2 + 1));
    if (base + 3 < NN) g_dinv[base + 3] = rsqrtf((float)(v3 + 1));

    int s = v0 + v1 + v2 + v3;
    sh[t] = s;
    __syncthreads();
#pragma unroll
    for (int off = 1; off < 256; off <<= 1) {
        int x = (t >= off) ? sh[t - off] : 0;
        __syncthreads();
        sh[t] += x;
        __syncthreads();
    }
    int excl = sh[t] - s;
    if (t == 255) g_bsum[blockIdx.x] = sh[255];
    if (base + 0 < NN) g_rowstart[base + 0] = excl;
    if (base + 1 < NN) g_rowstart[base + 1] = excl + v0;
    if (base + 2 < NN) g_rowstart[base + 2] = excl + v0 + v1;
    if (base + 3 < NN) g_rowstart[base + 3] = excl + v0 + v1 + v2;
}

// ----------------- scan of block sums fused into the add pass ---------------
__global__ __launch_bounds__(256) void k_scan3() {
    __shared__ int sh[128];
    int t = threadIdx.x;
    if (t < 128) {
        int v = (t < NBLK) ? g_bsum[t] : 0;
        sh[t] = v;
    }
    __syncthreads();
    // 128-wide inclusive scan done by the first 128 threads
    if (t < 128) {
#pragma unroll
        for (int off = 1; off < 128; off <<= 1) {
            int x = (t >= off) ? sh[t - off] : 0;
            __syncthreads();
            sh[t] += x;
            __syncthreads();
        }
    } else {
#pragma unroll
        for (int off = 1; off < 128; off <<= 1) {
            __syncthreads();
            __syncthreads();
        }
    }
    __syncthreads();
    int i = blockIdx.x * blockDim.x + t;
    if (i < NN) {
        int blk = i / SCAN_BLK;
        int pre = (blk == 0) ? 0 : sh[blk - 1];   // exclusive prefix
        g_rowstart[i] += pre;
        g_cursor[i] = 0;
    }
    if (i == 0) g_rowstart[NN] = NE;
}

// ------------------------------- CSR fill (reads edge index directly) -------
__global__ void k_fill(const void* __restrict__ ei) {
    int e = blockIdx.x * blockDim.x + threadIdx.x;
    if (e >= NE) return;
    int s, d;
    if (g_is64) {
        s = (int)((const long long*)ei)[e];
        d = (int)((const long long*)ei)[NE + e];
    } else {
        s = ((const int*)ei)[e];
        d = ((const int*)ei)[NE + e];
    }
    int pos = g_rowstart[d] + atomicAdd(&g_cursor[d], 1);
    g_csr_src[pos] = s;
}

// ---------------------------------------------- GEMM (2-pass split tf32) ----
// h = X @ W. Split A only: (a_hi + a_lo) * b_hi. Residual error a*b_lo
// ~2^-11 RMS -> h rel err ~1.6e-4 (verified acceptable in R14 at same eps).
__device__ __forceinline__ uint32_t f2tf32(float x) {
    uint32_t r;
    asm("cvt.rna.tf32.f32 %0, %1;" : "=r"(r) : "f"(x));
    return r;
}

__device__ __forceinline__ void mma8(float* c, const uint32_t* a,
                                     uint32_t b0, uint32_t b1) {
    asm volatile(
        "mma.sync.aligned.m16n8k8.row.col.f32.tf32.tf32.f32 "
        "{%0,%1,%2,%3}, {%4,%5,%6,%7}, {%8,%9}, {%0,%1,%2,%3};"
        : "+f"(c[0]), "+f"(c[1]), "+f"(c[2]), "+f"(c[3])
        : "r"(a[0]), "r"(a[1]), "r"(a[2]), "r"(a[3]), "r"(b0), "r"(b1));
}

#define BK 16
#define APAD 20
#define BPAD 136

__global__ __launch_bounds__(256) void k_gemm(const float* __restrict__ X,
                                              const float* __restrict__ W) {
    __shared__ uint32_t Ah[128 * APAD], Al[128 * APAD];
    __shared__ uint32_t Bh[BK * BPAD];

    int tid  = threadIdx.x;
    int lane = tid & 31;
    int w    = tid >> 5;
    int wm   = w >> 1;
    int wn   = w & 1;
    int gr   = lane >> 2;
    int gc   = lane & 3;
    int row0 = blockIdx.x * 128;

    float acc[2][8][4];
#pragma unroll
    for (int i = 0; i < 2; i++)
#pragma unroll
        for (int j = 0; j < 8; j++)
#pragma unroll
            for (int q = 0; q < 4; q++) acc[i][j][q] = 0.0f;

    for (int k0 = 0; k0 < 128; k0 += BK) {
#pragma unroll
        for (int r = 0; r < 2; r++) {
            int idx = tid + r * 256;
            int m   = idx >> 2;
            int kq  = (idx & 3) * 4;
            float4 v = (row0 + m < NN)
                ? *(const float4*)(X + (size_t)(row0 + m) * F + k0 + kq)
                : make_float4(0.f, 0.f, 0.f, 0.f);
            float vv[4] = {v.x, v.y, v.z, v.w};
#pragma unroll
            for (int q = 0; q < 4; q++) {
                uint32_t hi = f2tf32(vv[q]);
                float lo = vv[q] - __uint_as_float(hi);
                Ah[m * APAD + kq + q] = hi;
                Al[m * APAD + kq + q] = f2tf32(lo);
            }
        }
#pragma unroll
        for (int r = 0; r < 2; r++) {
            int idx = tid + r * 256;
            int k   = idx >> 5;
            int nq  = (idx & 31) * 4;
            float4 v = *(const float4*)(W + (size_t)(k0 + k) * F + nq);
            Bh[k * BPAD + nq + 0] = f2tf32(v.x);
            Bh[k * BPAD + nq + 1] = f2tf32(v.y);
            Bh[k * BPAD + nq + 2] = f2tf32(v.z);
            Bh[k * BPAD + nq + 3] = f2tf32(v.w);
        }
        __syncthreads();

#pragma unroll
        for (int ks = 0; ks < BK; ks += 8) {
            uint32_t a_hi[2][4], a_lo[2][4];
#pragma unroll
            for (int i = 0; i < 2; i++) {
                int mb = wm * 32 + i * 16;
                a_hi[i][0] = Ah[(mb + gr)     * APAD + ks + gc];
                a_hi[i][1] = Ah[(mb + gr + 8) * APAD + ks + gc];
                a_hi[i][2] = Ah[(mb + gr)     * APAD + ks + gc + 4];
                a_hi[i][3] = Ah[(mb + gr + 8) * APAD + ks + gc + 4];
                a_lo[i][0] = Al[(mb + gr)     * APAD + ks + gc];
                a_lo[i][1] = Al[(mb + gr + 8) * APAD + ks + gc];
                a_lo[i][2] = Al[(mb + gr)     * APAD + ks + gc + 4];
                a_lo[i][3] = Al[(mb + gr + 8) * APAD + ks + gc + 4];
            }
#pragma unroll
            for (int j = 0; j < 8; j++) {
                int nb = wn * 64 + j * 8;
                uint32_t bh0 = Bh[(ks + gc)     * BPAD + nb + gr];
                uint32_t bh1 = Bh[(ks + gc + 4) * BPAD + nb + gr];
#pragma unroll
                for (int i = 0; i < 2; i++) {
                    mma8(acc[i][j], a_hi[i], bh0, bh1);
                    mma8(acc[i][j], a_lo[i], bh0, bh1);
                }
            }
        }
        __syncthreads();
    }

#pragma unroll
    for (int i = 0; i < 2; i++) {
        int rbase = row0 + wm * 32 + i * 16;
#pragma unroll
        for (int j = 0; j < 8; j++) {
            int col = wn * 64 + j * 8 + 2 * gc;
            int r1 = rbase + gr;
            int r2 = rbase + gr + 8;
            if (r1 < NN)
                *(float2*)(g_h + (size_t)r1 * F + col) =
                    make_float2(acc[i][j][0], acc[i][j][1]);
            if (r2 < NN)
                *(float2*)(g_h + (size_t)r2 * F + col) =
                    make_float2(acc[i][j][2], acc[i][j][3]);
        }
    }
}

// ---------------------------------------------------------------- gather ----
// One warp per destination node; fp32 messages. Latency-bound -> unroll 8
// rows in flight, indices fetched as aligned int4 (1 broadcast LDG / 4 edges).
#define EDGE1(sv)                                                    \
    {                                                                \
        int s_ = (sv);                                               \
        float n_ = di * g_dinv[s_];                                  \
        float4 v_ = ((const float4*)(g_h + (size_t)s_ * F))[lane];   \
        ax = fmaf(v_.x, n_, ax); ay = fmaf(v_.y, n_, ay);            \
        az = fmaf(v_.z, n_, az); aw = fmaf(v_.w, n_, aw);            \
    }

__global__ __launch_bounds__(256) void k_gather(float* __restrict__ out,
                                                const float* __restrict__ b) {
    int node = (blockIdx.x * 256 + threadIdx.x) >> 5;
    if (node >= NN) return;
    int lane = threadIdx.x & 31;

    float di = g_dinv[node];
    float4 hv = ((const float4*)(g_h + (size_t)node * F))[lane];
    float sl = di * di;
    float ax = hv.x * sl, ay = hv.y * sl, az = hv.z * sl, aw = hv.w * sl;

    int e   = g_rowstart[node];
    int end = g_rowstart[node + 1];

    // peel to 16B alignment of &g_csr_src[e]
    while (e < end && (e & 3)) { EDGE1(g_csr_src[e]); e++; }

    for (; e + 8 <= end; e += 8) {
        int4 ia = *(const int4*)&g_csr_src[e];
        int4 ib = *(const int4*)&g_csr_src[e + 4];
        float n0 = di * g_dinv[ia.x];
        float n1 = di * g_dinv[ia.y];
        float n2 = di * g_dinv[ia.z];
        float n3 = di * g_dinv[ia.w];
        float n4 = di * g_dinv[ib.x];
        float n5 = di * g_dinv[ib.y];
        float n6 = di * g_dinv[ib.z];
        float n7 = di * g_dinv[ib.w];
        float4 v0 = ((const float4*)(g_h + (size_t)ia.x * F))[lane];
        float4 v1 = ((const float4*)(g_h + (size_t)ia.y * F))[lane];
        float4 v2 = ((const float4*)(g_h + (size_t)ia.z * F))[lane];
        float4 v3 = ((const float4*)(g_h + (size_t)ia.w * F))[lane];
        float4 v4 = ((const float4*)(g_h + (size_t)ib.x * F))[lane];
        float4 v5 = ((const float4*)(g_h + (size_t)ib.y * F))[lane];
        float4 v6 = ((const float4*)(g_h + (size_t)ib.z * F))[lane];
        float4 v7 = ((const float4*)(g_h + (size_t)ib.w * F))[lane];
        ax = fmaf(v0.x, n0, fmaf(v1.x, n1, fmaf(v2.x, n2, fmaf(v3.x, n3, ax))));
        ay = fmaf(v0.y, n0, fmaf(v1.y, n1, fmaf(v2.y, n2, fmaf(v3.y, n3, ay))));
        az = fmaf(v0.z, n0, fmaf(v1.z, n1, fmaf(v2.z, n2, fmaf(v3.z, n3, az))));
        aw = fmaf(v0.w, n0, fmaf(v1.w, n1, fmaf(v2.w, n2, fmaf(v3.w, n3, aw))));
        ax = fmaf(v4.x, n4, fmaf(v5.x, n5, fmaf(v6.x, n6, fmaf(v7.x, n7, ax))));
        ay = fmaf(v4.y, n4, fmaf(v5.y, n5, fmaf(v6.y, n6, fmaf(v7.y, n7, ay))));
        az = fmaf(v4.z, n4, fmaf(v5.z, n5, fmaf(v6.z, n6, fmaf(v7.z, n7, az))));
        aw = fmaf(v4.w, n4, fmaf(v5.w, n5, fmaf(v6.w, n6, fmaf(v7.w, n7, aw))));
    }
    for (; e + 4 <= end; e += 4) {
        int4 ia = *(const int4*)&g_csr_src[e];
        float n0 = di * g_dinv[ia.x];
        float n1 = di * g_dinv[ia.y];
        float n2 = di * g_dinv[ia.z];
        float n3 = di * g_dinv[ia.w];
        float4 v0 = ((const float4*)(g_h + (size_t)ia.x * F))[lane];
        float4 v1 = ((const float4*)(g_h + (size_t)ia.y * F))[lane];
        float4 v2 = ((const float4*)(g_h + (size_t)ia.z * F))[lane];
        float4 v3 = ((const float4*)(g_h + (size_t)ia.w * F))[lane];
        ax = fmaf(v0.x, n0, fmaf(v1.x, n1, fmaf(v2.x, n2, fmaf(v3.x, n3, ax))));
        ay = fmaf(v0.y, n0, fmaf(v1.y, n1, fmaf(v2.y, n2, fmaf(v3.y, n3, ay))));
        az = fmaf(v0.z, n0, fmaf(v1.z, n1, fmaf(v2.z, n2, fmaf(v3.z, n3, az))));
        aw = fmaf(v0.w, n0, fmaf(v1.w, n1, fmaf(v2.w, n2, fmaf(v3.w, n3, aw))));
    }
    for (; e < end; e++) EDGE1(g_csr_src[e]);

    float4 bv = ((const float4*)b)[lane];
    ((float4*)(out + (size_t)node * F))[lane] =
        make_float4(ax + bv.x, ay + bv.y, az + bv.z, aw + bv.w);
}

// ------------------------------------------------------------------ launch --
extern "C" void kernel_launch(void* const* d_in, const int* in_sizes, int n_in,
                              void* d_out, int out_size) {
    const float* x  = (const float*)d_in[0];   // [NN, F]
    const void*  ei = d_in[1];                 // [2, NE], int32 or int64
    const float* W  = (const float*)d_in[2];   // [F, F]
    const float* b  = (const float*)d_in[3];   // [F]
    float* out = (float*)d_out;                // [NN, F]

    k_detect_zero<<<(NN + 255) / 256, 256>>>((const int*)ei);
    k_count<<<(NE + 255) / 256, 256>>>(ei);

    k_scan1<<<NBLK, 256>>>();
    k_scan3<<<(NN + 255) / 256, 256>>>();
    k_fill<<<(NE + 255) / 256, 256>>>(ei);

    k_gemm<<<(NN + 127) / 128, 256>>>(x, W);

    k_gather<<<(NN * 32 + 255) / 256, 256>>>(out, b);
}

// round 16
// speedup vs baseline: 2.0449x; 1.1052x over previous
#include <cuda_runtime.h>
#include <cstdint>

#define NN 100000
#define NE 1600000
#define F  128
#define SCAN_BLK 1024
#define NBLK ((NN + SCAN_BLK - 1) / SCAN_BLK)   // 98

// Scratch (allocation-free rule: __device__ globals)
__device__ float g_h[(size_t)NN * F];   // h = x @ W
__device__ float g_dinv[NN];
__device__ int   g_deg[NN];
__device__ int   g_rowstart[NN + 1];
__device__ int   g_cursor[NN];
__device__ int   g_csr_src[NE];
__device__ int   g_bsum[128];
__device__ int   g_is64;

// --------------------------- detect edge dtype + zero degree (fused) --------
__global__ void k_detect_zero(const int* __restrict__ ei32) {
    int i = blockIdx.x * blockDim.x + threadIdx.x;
    if (i < NN) g_deg[i] = 0;
    if (blockIdx.x == 0) {
        __shared__ int nz;
        if (threadIdx.x == 0) nz = 0;
        __syncthreads();
        for (int k = threadIdx.x; k < 8192; k += blockDim.x)
            if (ei32[2 * k + 1] != 0) nz = 1;
        __syncthreads();
        if (threadIdx.x == 0) g_is64 = (nz == 0) ? 1 : 0;
    }
}

// ------------------------------- degree count (reads dst half directly) -----
__global__ void k_count(const void* __restrict__ ei) {
    int e = blockIdx.x * blockDim.x + threadIdx.x;
    if (e >= NE) return;
    int v = g_is64 ? (int)((const long long*)ei)[NE + e]
                   : ((const int*)ei)[NE + e];
    atomicAdd(&g_deg[v], 1);
}

// -------------------------------------- exclusive scan (+ dinv fused) -------
__global__ __launch_bounds__(256) void k_scan1() {
    __shared__ int sh[256];
    int t = threadIdx.x;
    int base = blockIdx.x * SCAN_BLK + t * 4;
    int v0 = 0, v1 = 0, v2 = 0, v3 = 0;
    if (base + 3 < NN) {
        int4 d = *(const int4*)&g_deg[base];
        v0 = d.x; v1 = d.y; v2 = d.z; v3 = d.w;
    } else {
        if (base + 0 < NN) v0 = g_deg[base + 0];
        if (base + 1 < NN) v1 = g_deg[base + 1];
        if (base + 2 < NN) v2 = g_deg[base + 2];
        if (base + 3 < NN) v3 = g_deg[base + 3];
    }
    if (base + 0 < NN) g_dinv[base + 0] = rsqrtf((float)(v0 + 1));
    if (base + 1 < NN) g_dinv[base + 1] = rsqrtf((float)(v1 + 1));
    if (base + 2 < NN) g_dinv[base + 2] = rsqrtf((float)(v2 + 1));
    if (base + 3 < NN) g_dinv[base + 3] = rsqrtf((float)(v3 + 1));

    int s = v0 + v1 + v2 + v3;
    sh[t] = s;
    __syncthreads();
#pragma unroll
    for (int off = 1; off < 256; off <<= 1) {
        int x = (t >= off) ? sh[t - off] : 0;
        __syncthreads();
        sh[t] += x;
        __syncthreads();
    }
    int excl = sh[t] - s;
    if (t == 255) g_bsum[blockIdx.x] = sh[255];
    if (base + 0 < NN) g_rowstart[base + 0] = excl;
    if (base + 1 < NN) g_rowstart[base + 1] = excl + v0;
    if (base + 2 < NN) g_rowstart[base + 2] = excl + v0 + v1;
    if (base + 3 < NN) g_rowstart[base + 3] = excl + v0 + v1 + v2;
}

// ----------------- scan of block sums fused into the add pass ---------------
__global__ __launch_bounds__(256) void k_scan3() {
    __shared__ int sh[128];
    int t = threadIdx.x;
    if (t < 128) {
        int v = (t < NBLK) ? g_bsum[t] : 0;
        sh[t] = v;
    }
    __syncthreads();
    if (t < 128) {
#pragma unroll
        for (int off = 1; off < 128; off <<= 1) {
            int x = (t >= off) ? sh[t - off] : 0;
            __syncthreads();
            sh[t] += x;
            __syncthreads();
        }
    } else {
#pragma unroll
        for (int off = 1; off < 128; off <<= 1) {
            __syncthreads();
            __syncthreads();
        }
    }
    __syncthreads();
    int i = blockIdx.x * blockDim.x + t;
    if (i < NN) {
        int blk = i / SCAN_BLK;
        int pre = (blk == 0) ? 0 : sh[blk - 1];   // exclusive prefix
        g_rowstart[i] += pre;
        g_cursor[i] = 0;
    }
    if (i == 0) g_rowstart[NN] = NE;
}

// ------------------------------- CSR fill (reads edge index directly) -------
__global__ void k_fill(const void* __restrict__ ei) {
    int e = blockIdx.x * blockDim.x + threadIdx.x;
    if (e >= NE) return;
    int s, d;
    if (g_is64) {
        s = (int)((const long long*)ei)[e];
        d = (int)((const long long*)ei)[NE + e];
    } else {
        s = ((const int*)ei)[e];
        d = ((const int*)ei)[NE + e];
    }
    int pos = g_rowstart[d] + atomicAdd(&g_cursor[d], 1);
    g_csr_src[pos] = s;
}

// ---------------------------------------------- GEMM (2-pass split tf32) ----
__device__ __forceinline__ uint32_t f2tf32(float x) {
    uint32_t r;
    asm("cvt.rna.tf32.f32 %0, %1;" : "=r"(r) : "f"(x));
    return r;
}

__device__ __forceinline__ void mma8(float* c, const uint32_t* a,
                                     uint32_t b0, uint32_t b1) {
    asm volatile(
        "mma.sync.aligned.m16n8k8.row.col.f32.tf32.tf32.f32 "
        "{%0,%1,%2,%3}, {%4,%5,%6,%7}, {%8,%9}, {%0,%1,%2,%3};"
        : "+f"(c[0]), "+f"(c[1]), "+f"(c[2]), "+f"(c[3])
        : "r"(a[0]), "r"(a[1]), "r"(a[2]), "r"(a[3]), "r"(b0), "r"(b1));
}

#define BK 16
#define APAD 20
#define BPAD 136

__global__ __launch_bounds__(256) void k_gemm(const float* __restrict__ X,
                                              const float* __restrict__ W) {
    __shared__ uint32_t Ah[128 * APAD], Al[128 * APAD];
    __shared__ uint32_t Bh[BK * BPAD];

    int tid  = threadIdx.x;
    int lane = tid & 31;
    int w    = tid >> 5;
    int wm   = w >> 1;
    int wn   = w & 1;
    int gr   = lane >> 2;
    int gc   = lane & 3;
    int row0 = blockIdx.x * 128;

    float acc[2][8][4];
#pragma unroll
    for (int i = 0; i < 2; i++)
#pragma unroll
        for (int j = 0; j < 8; j++)
#pragma unroll
            for (int q = 0; q < 4; q++) acc[i][j][q] = 0.0f;

    for (int k0 = 0; k0 < 128; k0 += BK) {
#pragma unroll
        for (int r = 0; r < 2; r++) {
            int idx = tid + r * 256;
            int m   = idx >> 2;
            int kq  = (idx & 3) * 4;
            float4 v = (row0 + m < NN)
                ? *(const float4*)(X + (size_t)(row0 + m) * F + k0 + kq)
                : make_float4(0.f, 0.f, 0.f, 0.f);
            float vv[4] = {v.x, v.y, v.z, v.w};
#pragma unroll
            for (int q = 0; q < 4; q++) {
                uint32_t hi = f2tf32(vv[q]);
                float lo = vv[q] - __uint_as_float(hi);
                Ah[m * APAD + kq + q] = hi;
                Al[m * APAD + kq + q] = f2tf32(lo);
            }
        }
#pragma unroll
        for (int r = 0; r < 2; r++) {
            int idx = tid + r * 256;
            int k   = idx >> 5;
            int nq  = (idx & 31) * 4;
            float4 v = *(const float4*)(W + (size_t)(k0 + k) * F + nq);
            Bh[k * BPAD + nq + 0] = f2tf32(v.x);
            Bh[k * BPAD + nq + 1] = f2tf32(v.y);
            Bh[k * BPAD + nq + 2] = f2tf32(v.z);
            Bh[k * BPAD + nq + 3] = f2tf32(v.w);
        }
        __syncthreads();

#pragma unroll
        for (int ks = 0; ks < BK; ks += 8) {
            uint32_t a_hi[2][4], a_lo[2][4];
#pragma unroll
            for (int i = 0; i < 2; i++) {
                int mb = wm * 32 + i * 16;
                a_hi[i][0] = Ah[(mb + gr)     * APAD + ks + gc];
                a_hi[i][1] = Ah[(mb + gr + 8) * APAD + ks + gc];
                a_hi[i][2] = Ah[(mb + gr)     * APAD + ks + gc + 4];
                a_hi[i][3] = Ah[(mb + gr + 8) * APAD + ks + gc + 4];
                a_lo[i][0] = Al[(mb + gr)     * APAD + ks + gc];
                a_lo[i][1] = Al[(mb + gr + 8) * APAD + ks + gc];
                a_lo[i][2] = Al[(mb + gr)     * APAD + ks + gc + 4];
                a_lo[i][3] = Al[(mb + gr + 8) * APAD + ks + gc + 4];
            }
#pragma unroll
            for (int j = 0; j < 8; j++) {
                int nb = wn * 64 + j * 8;
                uint32_t bh0 = Bh[(ks + gc)     * BPAD + nb + gr];
                uint32_t bh1 = Bh[(ks + gc + 4) * BPAD + nb + gr];
#pragma unroll
                for (int i = 0; i < 2; i++) {
                    mma8(acc[i][j], a_hi[i], bh0, bh1);
                    mma8(acc[i][j], a_lo[i], bh0, bh1);
                }
            }
        }
        __syncthreads();
    }

#pragma unroll
    for (int i = 0; i < 2; i++) {
        int rbase = row0 + wm * 32 + i * 16;
#pragma unroll
        for (int j = 0; j < 8; j++) {
            int col = wn * 64 + j * 8 + 2 * gc;
            int r1 = rbase + gr;
            int r2 = rbase + gr + 8;
            if (r1 < NN)
                *(float2*)(g_h + (size_t)r1 * F + col) =
                    make_float2(acc[i][j][0], acc[i][j][1]);
            if (r2 < NN)
                *(float2*)(g_h + (size_t)r2 * F + col) =
                    make_float2(acc[i][j][2], acc[i][j][3]);
        }
    }
}

// ---------------------------------------------------------------- gather ----
#define EDGE1(sv)                                                    \
    {                                                                \
        int s_ = (sv);                                               \
        float n_ = di * g_dinv[s_];                                  \
        float4 v_ = ((const float4*)(g_h + (size_t)s_ * F))[lane];   \
        ax = fmaf(v_.x, n_, ax); ay = fmaf(v_.y, n_, ay);            \
        az = fmaf(v_.z, n_, az); aw = fmaf(v_.w, n_, aw);            \
    }

__global__ __launch_bounds__(256) void k_gather(float* __restrict__ out,
                                                const float* __restrict__ b) {
    int node = (blockIdx.x * 256 + threadIdx.x) >> 5;
    if (node >= NN) return;
    int lane = threadIdx.x & 31;

    float di = g_dinv[node];
    float4 hv = ((const float4*)(g_h + (size_t)node * F))[lane];
    float sl = di * di;
    float ax = hv.x * sl, ay = hv.y * sl, az = hv.z * sl, aw = hv.w * sl;

    int e   = g_rowstart[node];
    int end = g_rowstart[node + 1];

    while (e < end && (e & 3)) { EDGE1(g_csr_src[e]); e++; }

    for (; e + 8 <= end; e += 8) {
        int4 ia = *(const int4*)&g_csr_src[e];
        int4 ib = *(const int4*)&g_csr_src[e + 4];
        float n0 = di * g_dinv[ia.x];
        float n1 = di * g_dinv[ia.y];
        float n2 = di * g_dinv[ia.z];
        float n3 = di * g_dinv[ia.w];
        float n4 = di * g_dinv[ib.x];
        float n5 = di * g_dinv[ib.y];
        float n6 = di * g_dinv[ib.z];
        float n7 = di * g_dinv[ib.w];
        float4 v0 = ((const float4*)(g_h + (size_t)ia.x * F))[lane];
        float4 v1 = ((const float4*)(g_h + (size_t)ia.y * F))[lane];
        float4 v2 = ((const float4*)(g_h + (size_t)ia.z * F))[lane];
        float4 v3 = ((const float4*)(g_h + (size_t)ia.w * F))[lane];
        float4 v4 = ((const float4*)(g_h + (size_t)ib.x * F))[lane];
        float4 v5 = ((const float4*)(g_h + (size_t)ib.y * F))[lane];
        float4 v6 = ((const float4*)(g_h + (size_t)ib.z * F))[lane];
        float4 v7 = ((const float4*)(g_h + (size_t)ib.w * F))[lane];
        ax = fmaf(v0.x, n0, fmaf(v1.x, n1, fmaf(v2.x, n2, fmaf(v3.x, n3, ax))));
        ay = fmaf(v0.y, n0, fmaf(v1.y, n1, fmaf(v2.y, n2, fmaf(v3.y, n3, ay))));
        az = fmaf(v0.z, n0, fmaf(v1.z, n1, fmaf(v2.z, n2, fmaf(v3.z, n3, az))));
        aw = fmaf(v0.w, n0, fmaf(v1.w, n1, fmaf(v2.w, n2, fmaf(v3.w, n3, aw))));
        ax = fmaf(v4.x, n4, fmaf(v5.x, n5, fmaf(v6.x, n6, fmaf(v7.x, n7, ax))));
        ay = fmaf(v4.y, n4, fmaf(v5.y, n5, fmaf(v6.y, n6, fmaf(v7.y, n7, ay))));
        az = fmaf(v4.z, n4, fmaf(v5.z, n5, fmaf(v6.z, n6, fmaf(v7.z, n7, az))));
        aw = fmaf(v4.w, n4, fmaf(v5.w, n5, fmaf(v6.w, n6, fmaf(v7.w, n7, aw))));
    }
    for (; e + 4 <= end; e += 4) {
        int4 ia = *(const int4*)&g_csr_src[e];
        float n0 = di * g_dinv[ia.x];
        float n1 = di * g_dinv[ia.y];
        float n2 = di * g_dinv[ia.z];
        float n3 = di * g_dinv[ia.w];
        float4 v0 = ((const float4*)(g_h + (size_t)ia.x * F))[lane];
        float4 v1 = ((const float4*)(g_h + (size_t)ia.y * F))[lane];
        float4 v2 = ((const float4*)(g_h + (size_t)ia.z * F))[lane];
        float4 v3 = ((const float4*)(g_h + (size_t)ia.w * F))[lane];
        ax = fmaf(v0.x, n0, fmaf(v1.x, n1, fmaf(v2.x, n2, fmaf(v3.x, n3, ax))));
        ay = fmaf(v0.y, n0, fmaf(v1.y, n1, fmaf(v2.y, n2, fmaf(v3.y, n3, ay))));
        az = fmaf(v0.z, n0, fmaf(v1.z, n1, fmaf(v2.z, n2, fmaf(v3.z, n3, az))));
        aw = fmaf(v0.w, n0, fmaf(v1.w, n1, fmaf(v2.w, n2, fmaf(v3.w, n3, aw))));
    }
    for (; e < end; e++) EDGE1(g_csr_src[e]);

    float4 bv = ((const float4*)b)[lane];
    ((float4*)(out + (size_t)node * F))[lane] =
        make_float4(ax + bv.x, ay + bv.y, az + bv.z, aw + bv.w);
}

// ------------------------------------------------------------------ launch --
// Fork/join: GEMM (depends only on x,W) runs on a side stream concurrently
// with the edge-prep chain (depends only on edge_index). Join before gather.
// Stream/event create+destroy are host-side (legal during capture, free at
// graph replay); no syncs, no allocations.
extern "C" void kernel_launch(void* const* d_in, const int* in_sizes, int n_in,
                              void* d_out, int out_size) {
    const float* x  = (const float*)d_in[0];   // [NN, F]
    const void*  ei = d_in[1];                 // [2, NE], int32 or int64
    const float* W  = (const float*)d_in[2];   // [F, F]
    const float* b  = (const float*)d_in[3];   // [F]
    float* out = (float*)d_out;                // [NN, F]

    cudaStream_t s2;
    cudaStreamCreateWithFlags(&s2, cudaStreamNonBlocking);
    cudaEvent_t evFork, evJoin;
    cudaEventCreateWithFlags(&evFork, cudaEventDisableTiming);
    cudaEventCreateWithFlags(&evJoin, cudaEventDisableTiming);

    // Fork side branch: GEMM
    cudaEventRecord(evFork, 0);
    cudaStreamWaitEvent(s2, evFork, 0);
    k_gemm<<<(NN + 127) / 128, 256, 0, s2>>>(x, W);
    cudaEventRecord(evJoin, s2);

    // Main branch: edge prep chain
    k_detect_zero<<<(NN + 255) / 256, 256>>>((const int*)ei);
    k_count<<<(NE + 255) / 256, 256>>>(ei);
    k_scan1<<<NBLK, 256>>>();
    k_scan3<<<(NN + 255) / 256, 256>>>();
    k_fill<<<(NE + 255) / 256, 256>>>(ei);

    // Join, then gather
    cudaStreamWaitEvent(0, evJoin, 0);
    k_gather<<<(NN * 32 + 255) / 256, 256>>>(out, b);

    cudaEventDestroy(evFork);
    cudaEventDestroy(evJoin);
    cudaStreamDestroy(s2);
}

// round 17
// speedup vs baseline: 2.0509x; 1.0029x over previous
#include <cuda_runtime.h>
#include <cstdint>

#define NN 100000
#define NE 1600000
#define F  128
#define SCAN_BLK 1024
#define NBLK ((NN + SCAN_BLK - 1) / SCAN_BLK)   // 98

// Scratch (allocation-free rule: __device__ globals)
__device__ float g_h[(size_t)NN * F];   // h = x @ W
__device__ float g_dinv[NN];
__device__ int   g_deg[NN];
__device__ int   g_rowstart[NN + 1];
__device__ int   g_cursor[NN];
__device__ int   g_csr_src[NE];
__device__ int   g_bsum[128];
__device__ int   g_is64;

// --------------------------- detect edge dtype + zero degree (fused) --------
__global__ void k_detect_zero(const int* __restrict__ ei32) {
    int i = blockIdx.x * blockDim.x + threadIdx.x;
    if (i < NN) g_deg[i] = 0;
    if (blockIdx.x == 0) {
        __shared__ int nz;
        if (threadIdx.x == 0) nz = 0;
        __syncthreads();
        for (int k = threadIdx.x; k < 8192; k += blockDim.x)
            if (ei32[2 * k + 1] != 0) nz = 1;
        __syncthreads();
        if (threadIdx.x == 0) g_is64 = (nz == 0) ? 1 : 0;
    }
}

// ------------------------------- degree count (reads dst half directly) -----
__global__ void k_count(const void* __restrict__ ei) {
    int e = blockIdx.x * blockDim.x + threadIdx.x;
    if (e >= NE) return;
    int v = g_is64 ? (int)((const long long*)ei)[NE + e]
                   : ((const int*)ei)[NE + e];
    atomicAdd(&g_deg[v], 1);
}

// -------------------------------------- exclusive scan (+ dinv fused) -------
__global__ __launch_bounds__(256) void k_scan1() {
    __shared__ int sh[256];
    int t = threadIdx.x;
    int base = blockIdx.x * SCAN_BLK + t * 4;
    int v0 = 0, v1 = 0, v2 = 0, v3 = 0;
    if (base + 3 < NN) {
        int4 d = *(const int4*)&g_deg[base];
        v0 = d.x; v1 = d.y; v2 = d.z; v3 = d.w;
    } else {
        if (base + 0 < NN) v0 = g_deg[base + 0];
        if (base + 1 < NN) v1 = g_deg[base + 1];
        if (base + 2 < NN) v2 = g_deg[base + 2];
        if (base + 3 < NN) v3 = g_deg[base + 3];
    }
    if (base + 0 < NN) g_dinv[base + 0] = rsqrtf((float)(v0 + 1));
    if (base + 1 < NN) g_dinv[base + 1] = rsqrtf((float)(v1 + 1));
    if (base + 2 < NN) g_dinv[base + 2] = rsqrtf((float)(v2 + 1));
    if (base + 3 < NN) g_dinv[base + 3] = rsqrtf((float)(v3 + 1));

    int s = v0 + v1 + v2 + v3;
    sh[t] = s;
    __syncthreads();
#pragma unroll
    for (int off = 1; off < 256; off <<= 1) {
        int x = (t >= off) ? sh[t - off] : 0;
        __syncthreads();
        sh[t] += x;
        __syncthreads();
    }
    int excl = sh[t] - s;
    if (t == 255) g_bsum[blockIdx.x] = sh[255];
    if (base + 0 < NN) g_rowstart[base + 0] = excl;
    if (base + 1 < NN) g_rowstart[base + 1] = excl + v0;
    if (base + 2 < NN) g_rowstart[base + 2] = excl + v0 + v1;
    if (base + 3 < NN) g_rowstart[base + 3] = excl + v0 + v1 + v2;
}

// ----------------- scan of block sums fused into the add pass ---------------
__global__ __launch_bounds__(256) void k_scan3() {
    __shared__ int sh[128];
    int t = threadIdx.x;
    if (t < 128) {
        int v = (t < NBLK) ? g_bsum[t] : 0;
        sh[t] = v;
    }
    __syncthreads();
    if (t < 128) {
#pragma unroll
        for (int off = 1; off < 128; off <<= 1) {
            int x = (t >= off) ? sh[t - off] : 0;
            __syncthreads();
            sh[t] += x;
            __syncthreads();
        }
    } else {
#pragma unroll
        for (int off = 1; off < 128; off <<= 1) {
            __syncthreads();
            __syncthreads();
        }
    }
    __syncthreads();
    int i = blockIdx.x * blockDim.x + t;
    if (i < NN) {
        int blk = i / SCAN_BLK;
        int pre = (blk == 0) ? 0 : sh[blk - 1];   // exclusive prefix
        g_rowstart[i] += pre;
        g_cursor[i] = 0;
    }
    if (i == 0) g_rowstart[NN] = NE;
}

// ------------------------------- CSR fill (reads edge index directly) -------
__global__ void k_fill(const void* __restrict__ ei) {
    int e = blockIdx.x * blockDim.x + threadIdx.x;
    if (e >= NE) return;
    int s, d;
    if (g_is64) {
        s = (int)((const long long*)ei)[e];
        d = (int)((const long long*)ei)[NE + e];
    } else {
        s = ((const int*)ei)[e];
        d = ((const int*)ei)[NE + e];
    }
    int pos = g_rowstart[d] + atomicAdd(&g_cursor[d], 1);
    g_csr_src[pos] = s;
}

// ---------------------------------------------- GEMM (2-pass split tf32) ----
__device__ __forceinline__ uint32_t f2tf32(float x) {
    uint32_t r;
    asm("cvt.rna.tf32.f32 %0, %1;" : "=r"(r) : "f"(x));
    return r;
}

__device__ __forceinline__ void mma8(float* c, const uint32_t* a,
                                     uint32_t b0, uint32_t b1) {
    asm volatile(
        "mma.sync.aligned.m16n8k8.row.col.f32.tf32.tf32.f32 "
        "{%0,%1,%2,%3}, {%4,%5,%6,%7}, {%8,%9}, {%0,%1,%2,%3};"
        : "+f"(c[0]), "+f"(c[1]), "+f"(c[2]), "+f"(c[3])
        : "r"(a[0]), "r"(a[1]), "r"(a[2]), "r"(a[3]), "r"(b0), "r"(b1));
}

#define BK 16
#define APAD 20
#define BPAD 136

__global__ __launch_bounds__(256) void k_gemm(const float* __restrict__ X,
                                              const float* __restrict__ W) {
    __shared__ uint32_t Ah[128 * APAD], Al[128 * APAD];
    __shared__ uint32_t Bh[BK * BPAD];

    int tid  = threadIdx.x;
    int lane = tid & 31;
    int w    = tid >> 5;
    int wm   = w >> 1;
    int wn   = w & 1;
    int gr   = lane >> 2;
    int gc   = lane & 3;
    int row0 = blockIdx.x * 128;

    float acc[2][8][4];
#pragma unroll
    for (int i = 0; i < 2; i++)
#pragma unroll
        for (int j = 0; j < 8; j++)
#pragma unroll
            for (int q = 0; q < 4; q++) acc[i][j][q] = 0.0f;

    for (int k0 = 0; k0 < 128; k0 += BK) {
#pragma unroll
        for (int r = 0; r < 2; r++) {
            int idx = tid + r * 256;
            int m   = idx >> 2;
            int kq  = (idx & 3) * 4;
            float4 v = (row0 + m < NN)
                ? *(const float4*)(X + (size_t)(row0 + m) * F + k0 + kq)
                : make_float4(0.f, 0.f, 0.f, 0.f);
            float vv[4] = {v.x, v.y, v.z, v.w};
#pragma unroll
            for (int q = 0; q < 4; q++) {
                uint32_t hi = f2tf32(vv[q]);
                float lo = vv[q] - __uint_as_float(hi);
                Ah[m * APAD + kq + q] = hi;
                Al[m * APAD + kq + q] = f2tf32(lo);
            }
        }
#pragma unroll
        for (int r = 0; r < 2; r++) {
            int idx = tid + r * 256;
            int k   = idx >> 5;
            int nq  = (idx & 31) * 4;
            float4 v = *(const float4*)(W + (size_t)(k0 + k) * F + nq);
            Bh[k * BPAD + nq + 0] = f2tf32(v.x);
            Bh[k * BPAD + nq + 1] = f2tf32(v.y);
            Bh[k * BPAD + nq + 2] = f2tf32(v.z);
            Bh[k * BPAD + nq + 3] = f2tf32(v.w);
        }
        __syncthreads();

#pragma unroll
        for (int ks = 0; ks < BK; ks += 8) {
            uint32_t a_hi[2][4], a_lo[2][4];
#pragma unroll
            for (int i = 0; i < 2; i++) {
                int mb = wm * 32 + i * 16;
                a_hi[i][0] = Ah[(mb + gr)     * APAD + ks + gc];
                a_hi[i][1] = Ah[(mb + gr + 8) * APAD + ks + gc];
                a_hi[i][2] = Ah[(mb + gr)     * APAD + ks + gc + 4];
                a_hi[i][3] = Ah[(mb + gr + 8) * APAD + ks + gc + 4];
                a_lo[i][0] = Al[(mb + gr)     * APAD + ks + gc];
                a_lo[i][1] = Al[(mb + gr + 8) * APAD + ks + gc];
                a_lo[i][2] = Al[(mb + gr)     * APAD + ks + gc + 4];
                a_lo[i][3] = Al[(mb + gr + 8) * APAD + ks + gc + 4];
            }
#pragma unroll
            for (int j = 0; j < 8; j++) {
                int nb = wn * 64 + j * 8;
                uint32_t bh0 = Bh[(ks + gc)     * BPAD + nb + gr];
                uint32_t bh1 = Bh[(ks + gc + 4) * BPAD + nb + gr];
#pragma unroll
                for (int i = 0; i < 2; i++) {
                    mma8(acc[i][j], a_hi[i], bh0, bh1);
                    mma8(acc[i][j], a_lo[i], bh0, bh1);
                }
            }
        }
        __syncthreads();
    }

#pragma unroll
    for (int i = 0; i < 2; i++) {
        int rbase = row0 + wm * 32 + i * 16;
#pragma unroll
        for (int j = 0; j < 8; j++) {
            int col = wn * 64 + j * 8 + 2 * gc;
            int r1 = rbase + gr;
            int r2 = rbase + gr + 8;
            if (r1 < NN)
                *(float2*)(g_h + (size_t)r1 * F + col) =
                    make_float2(acc[i][j][0], acc[i][j][1]);
            if (r2 < NN)
                *(float2*)(g_h + (size_t)r2 * F + col) =
                    make_float2(acc[i][j][2], acc[i][j][3]);
        }
    }
}

// ---------------------------------------------------------------- gather ----
#define EDGE1(sv)                                                    \
    {                                                                \
        int s_ = (sv);                                               \
        float n_ = di * g_dinv[s_];                                  \
        float4 v_ = ((const float4*)(g_h + (size_t)s_ * F))[lane];   \
        ax = fmaf(v_.x, n_, ax); ay = fmaf(v_.y, n_, ay);            \
        az = fmaf(v_.z, n_, az); aw = fmaf(v_.w, n_, aw);            \
    }

__global__ __launch_bounds__(256) void k_gather(float* __restrict__ out,
                                                const float* __restrict__ b) {
    int node = (blockIdx.x * 256 + threadIdx.x) >> 5;
    if (node >= NN) return;
    int lane = threadIdx.x & 31;

    float di = g_dinv[node];
    float4 hv = ((const float4*)(g_h + (size_t)node * F))[lane];
    float sl = di * di;
    float ax = hv.x * sl, ay = hv.y * sl, az = hv.z * sl, aw = hv.w * sl;

    int e   = g_rowstart[node];
    int end = g_rowstart[node + 1];

    while (e < end && (e & 3)) { EDGE1(g_csr_src[e]); e++; }

    for (; e + 8 <= end; e += 8) {
        int4 ia = *(const int4*)&g_csr_src[e];
        int4 ib = *(const int4*)&g_csr_src[e + 4];
        float n0 = di * g_dinv[ia.x];
        float n1 = di * g_dinv[ia.y];
        float n2 = di * g_dinv[ia.z];
        float n3 = di * g_dinv[ia.w];
        float n4 = di * g_dinv[ib.x];
        float n5 = di * g_dinv[ib.y];
        float n6 = di * g_dinv[ib.z];
        float n7 = di * g_dinv[ib.w];
        float4 v0 = ((const float4*)(g_h + (size_t)ia.x * F))[lane];
        float4 v1 = ((const float4*)(g_h + (size_t)ia.y * F))[lane];
        float4 v2 = ((const float4*)(g_h + (size_t)ia.z * F))[lane];
        float4 v3 = ((const float4*)(g_h + (size_t)ia.w * F))[lane];
        float4 v4 = ((const float4*)(g_h + (size_t)ib.x * F))[lane];
        float4 v5 = ((const float4*)(g_h + (size_t)ib.y * F))[lane];
        float4 v6 = ((const float4*)(g_h + (size_t)ib.z * F))[lane];
        float4 v7 = ((const float4*)(g_h + (size_t)ib.w * F))[lane];
        ax = fmaf(v0.x, n0, fmaf(v1.x, n1, fmaf(v2.x, n2, fmaf(v3.x, n3, ax))));
        ay = fmaf(v0.y, n0, fmaf(v1.y, n1, fmaf(v2.y, n2, fmaf(v3.y, n3, ay))));
        az = fmaf(v0.z, n0, fmaf(v1.z, n1, fmaf(v2.z, n2, fmaf(v3.z, n3, az))));
        aw = fmaf(v0.w, n0, fmaf(v1.w, n1, fmaf(v2.w, n2, fmaf(v3.w, n3, aw))));
        ax = fmaf(v4.x, n4, fmaf(v5.x, n5, fmaf(v6.x, n6, fmaf(v7.x, n7, ax))));
        ay = fmaf(v4.y, n4, fmaf(v5.y, n5, fmaf(v6.y, n6, fmaf(v7.y, n7, ay))));
        az = fmaf(v4.z, n4, fmaf(v5.z, n5, fmaf(v6.z, n6, fmaf(v7.z, n7, az))));
        aw = fmaf(v4.w, n4, fmaf(v5.w, n5, fmaf(v6.w, n6, fmaf(v7.w, n7, aw))));
    }
    for (; e + 4 <= end; e += 4) {
        int4 ia = *(const int4*)&g_csr_src[e];
        float n0 = di * g_dinv[ia.x];
        float n1 = di * g_dinv[ia.y];
        float n2 = di * g_dinv[ia.z];
        float n3 = di * g_dinv[ia.w];
        float4 v0 = ((const float4*)(g_h + (size_t)ia.x * F))[lane];
        float4 v1 = ((const float4*)(g_h + (size_t)ia.y * F))[lane];
        float4 v2 = ((const float4*)(g_h + (size_t)ia.z * F))[lane];
        float4 v3 = ((const float4*)(g_h + (size_t)ia.w * F))[lane];
        ax = fmaf(v0.x, n0, fmaf(v1.x, n1, fmaf(v2.x, n2, fmaf(v3.x, n3, ax))));
        ay = fmaf(v0.y, n0, fmaf(v1.y, n1, fmaf(v2.y, n2, fmaf(v3.y, n3, ay))));
        az = fmaf(v0.z, n0, fmaf(v1.z, n1, fmaf(v2.z, n2, fmaf(v3.z, n3, az))));
        aw = fmaf(v0.w, n0, fmaf(v1.w, n1, fmaf(v2.w, n2, fmaf(v3.w, n3, aw))));
    }
    for (; e < end; e++) EDGE1(g_csr_src[e]);

    float4 bv = ((const float4*)b)[lane];
    ((float4*)(out + (size_t)node * F))[lane] =
        make_float4(ax + bv.x, ay + bv.y, az + bv.z, aw + bv.w);
}

// ------------------------------------------------------------------ launch --
// Fork/join: GEMM (depends only on x,W) runs on a side stream concurrently
// with the edge-prep chain (depends only on edge_index). Join before gather.
// Stream/event create+destroy are host-side (legal during capture, free at
// graph replay); no syncs, no allocations.
extern "C" void kernel_launch(void* const* d_in, const int* in_sizes, int n_in,
                              void* d_out, int out_size) {
    const float* x  = (const float*)d_in[0];   // [NN, F]
    const void*  ei = d_in[1];                 // [2, NE], int32 or int64
    const float* W  = (const float*)d_in[2];   // [F, F]
    const float* b  = (const float*)d_in[3];   // [F]
    float* out = (float*)d_out;                // [NN, F]

    cudaStream_t s2;
    cudaStreamCreateWithFlags(&s2, cudaStreamNonBlocking);
    cudaEvent_t evFork, evJoin;
    cudaEventCreateWithFlags(&evFork, cudaEventDisableTiming);
    cudaEventCreateWithFlags(&evJoin, cudaEventDisableTiming);

    // Fork side branch: GEMM
    cudaEventRecord(evFork, 0);
    cudaStreamWaitEvent(s2, evFork, 0);
    k_gemm<<<(NN + 127) / 128, 256, 0, s2>>>(x, W);
    cudaEventRecord(evJoin, s2);

    // Main branch: edge prep chain
    k_detect_zero<<<(NN + 255) / 256, 256>>>((const int*)ei);
    k_count<<<(NE + 255) / 256, 256>>>(ei);
    k_scan1<<<NBLK, 256>>>();
    k_scan3<<<(NN + 255) / 256, 256>>>();
    k_fill<<<(NE + 255) / 256, 256>>>(ei);

    // Join, then gather
    cudaStreamWaitEvent(0, evJoin, 0);
    k_gather<<<(NN * 32 + 255) / 256, 256>>>(out, b);

    cudaEventDestroy(evFork);
    cudaEventDestroy(evJoin);
    cudaStreamDestroy(s2);
}